// round 17
// baseline (speedup 1.0000x reference)
#include <cuda_runtime.h>
#include <cuda_bf16.h>
#include <math.h>
#include <stdint.h>

// Problem constants
#define S_LEN   4096
#define HIDDEN  2304
#define NH      8
#define NKV     4
#define HD      256
#define QKVN    4096
#define SWIN    2048
#define SCALE_F 0.0625f
#define CAP_F   50.0f

#define KU_A 1152   // 2304/2 u32 per row
#define KU_O 1024   // 2048/2

// Scratch (device globals)
__device__ float g_qkv[(size_t)S_LEN * QKVN];
__device__ float g_ao[(size_t)S_LEN * (NH * HD)];
// attention pre-split K/V (proven)
__device__ uint32_t gKh[(size_t)NKV * S_LEN * 128];
__device__ uint32_t gKl[(size_t)NKV * S_LEN * 128];
__device__ uint32_t gVh[(size_t)NKV * HD * (S_LEN / 2)];
__device__ uint32_t gVl[(size_t)NKV * HD * (S_LEN / 2)];
// GEMM pre-split operands (bf16 hi/lo packed u32 pairs)
__device__ uint32_t gXh[(size_t)S_LEN * KU_A],  gXl[(size_t)S_LEN * KU_A];   // hidden
__device__ uint32_t gWh[(size_t)4096 * KU_A],   gWl[(size_t)4096 * KU_A];    // Wq|Wk|Wv
__device__ uint32_t gOh[(size_t)S_LEN * KU_O],  gOl[(size_t)S_LEN * KU_O];   // ao
__device__ uint32_t gWoh[(size_t)HIDDEN * KU_O], gWol[(size_t)HIDDEN * KU_O];// Wo

// ---------------------------------------------------------------------------
// Shared helpers
// ---------------------------------------------------------------------------
__device__ __forceinline__ void mma_bf16(float* d,
    uint32_t a0, uint32_t a1, uint32_t a2, uint32_t a3, uint32_t b0, uint32_t b1)
{
    asm volatile(
        "mma.sync.aligned.m16n8k16.row.col.f32.bf16.bf16.f32 "
        "{%0,%1,%2,%3}, {%4,%5,%6,%7}, {%8,%9}, {%0,%1,%2,%3};\n"
        : "+f"(d[0]), "+f"(d[1]), "+f"(d[2]), "+f"(d[3])
        : "r"(a0), "r"(a1), "r"(a2), "r"(a3), "r"(b0), "r"(b1));
}

__device__ __forceinline__ void split2(float x, float y, uint32_t& hi, uint32_t& lo)
{
    __nv_bfloat16 hx = __float2bfloat16_rn(x);
    __nv_bfloat16 hy = __float2bfloat16_rn(y);
    __nv_bfloat16 lx = __float2bfloat16_rn(x - __bfloat162float(hx));
    __nv_bfloat16 ly = __float2bfloat16_rn(y - __bfloat162float(hy));
    __nv_bfloat162 h2 = __halves2bfloat162(hx, hy);
    __nv_bfloat162 l2 = __halves2bfloat162(lx, ly);
    hi = *(uint32_t*)&h2;
    lo = *(uint32_t*)&l2;
}

__device__ __forceinline__ void cpa16(uint32_t dst_smem, const uint32_t* src)
{
    asm volatile("cp.async.ca.shared.global [%0], [%1], 16;\n"
                 :: "r"(dst_smem), "l"(src));
}

__device__ __forceinline__ float ex2_approx(float x)
{
    float r; asm("ex2.approx.f32 %0, %1;" : "=f"(r) : "f"(x)); return r;
}
__device__ __forceinline__ float rcp_approx(float x)
{
    float r; asm("rcp.approx.f32 %0, %1;" : "=f"(r) : "f"(x)); return r;
}
__device__ __forceinline__ void ldsm4(uint32_t& r0, uint32_t& r1, uint32_t& r2,
                                      uint32_t& r3, uint32_t addr)
{
    asm volatile("ldmatrix.sync.aligned.m8n8.x4.shared.b16 {%0,%1,%2,%3}, [%4];"
                 : "=r"(r0), "=r"(r1), "=r"(r2), "=r"(r3) : "r"(addr));
}

// ---------------------------------------------------------------------------
// split_mat: fp32 [rows x 2*ku] -> hi/lo u32 [rows x ku]
// ---------------------------------------------------------------------------
__global__ void split_mat(const float* __restrict__ src,
                          uint32_t* __restrict__ dh, uint32_t* __restrict__ dl, int ku)
{
    const size_t row = blockIdx.x;
    const float* s = src + row * (size_t)ku * 2;
    uint32_t* ph = dh + row * (size_t)ku;
    uint32_t* pl = dl + row * (size_t)ku;
    for (int j = threadIdx.x; j < ku; j += blockDim.x) {
        float2 v = *(const float2*)(s + 2 * j);
        uint32_t hi, lo;
        split2(v.x, v.y, hi, lo);
        ph[j] = hi; pl[j] = lo;
    }
}

// ---------------------------------------------------------------------------
// gemm_bf16p: pre-split bf16 hi/lo GEMM, cp.async double-buffered.
// C[m,n] = sum_k A[m,k]*B[n,k]; 3-pass AhBh+AhBl+AlBh (same order as proven
// gemm_bf16s -> identical accumulation, identical rel_err expected).
// 128x128 tile, 8 warps (warp tile 32x64), K-chunk 32 floats (16 u32/row).
// Smem: 2 stages x 4 mats x [128][20] u32 = 80KB dynamic. Stride 20 -> all
// fragment loads conflict-free (banks 20g+c4 distinct across warp).
// ---------------------------------------------------------------------------
#define GSTR2 20
#define GMAT (128 * GSTR2)      // 2560 u32 per matrix
#define GSTG (4 * GMAT)         // 10240 u32 per stage
#define GEMM_SMEM_BYTES (2 * GSTG * 4)   // 81920

__global__ void __launch_bounds__(256) gemm_bf16p(
    const uint32_t* __restrict__ Ah_, const uint32_t* __restrict__ Al_,
    const uint32_t* __restrict__ Bh_, const uint32_t* __restrict__ Bl_,
    float* __restrict__ C, int K, int ku, int ldc)
{
    extern __shared__ uint32_t smG[];

    const int tid  = threadIdx.x;
    const int warp = tid >> 5, lane = tid & 31;
    const int g    = lane >> 2, c4 = lane & 3;
    const int wm   = (warp >> 1) * 32, wn = (warp & 1) * 64;
    const int bm   = blockIdx.y * 128, bn = blockIdx.x * 128;
    const uint32_t smem_u32 = (uint32_t)__cvta_generic_to_shared(smG);

    // staging map: row = tid>>1 (0..127), chunk pair = (tid&1)*2
    const int srow = tid >> 1;
    const int scp  = (tid & 1) * 2;
    const uint32_t* pAh = Ah_ + (size_t)(bm + srow) * ku + scp * 4;
    const uint32_t* pAl = Al_ + (size_t)(bm + srow) * ku + scp * 4;
    const uint32_t* pBh = Bh_ + (size_t)(bn + srow) * ku + scp * 4;
    const uint32_t* pBl = Bl_ + (size_t)(bn + srow) * ku + scp * 4;

    auto stage = [&](int ck, int b) {
        const int kc0 = ck * 16;   // u32 col offset of chunk
        const uint32_t dbase = smem_u32 + (uint32_t)(b * GSTG + srow * GSTR2 + scp * 4) * 4;
#pragma unroll
        for (int c = 0; c < 2; c++) {
            const uint32_t d = dbase + c * 16;
            const size_t s = (size_t)kc0 + c * 4;
            cpa16(d,                    pAh + s);
            cpa16(d + GMAT * 4,         pAl + s);
            cpa16(d + 2 * GMAT * 4,     pBh + s);
            cpa16(d + 3 * GMAT * 4,     pBl + s);
        }
        asm volatile("cp.async.commit_group;\n" ::: "memory");
    };

    float acc[2][8][4];
#pragma unroll
    for (int i = 0; i < 2; i++)
#pragma unroll
        for (int j = 0; j < 8; j++)
#pragma unroll
            for (int t = 0; t < 4; t++) acc[i][j][t] = 0.f;

    const int nc = K >> 5;   // K / 32
    stage(0, 0);

    for (int ch = 0; ch < nc; ch++) {
        const int p = ch & 1;
        __syncthreads();                 // prev compute done with buf p^1
        if (ch + 1 < nc) {
            stage(ch + 1, p ^ 1);
            asm volatile("cp.async.wait_group 1;\n" ::: "memory");
        } else {
            asm volatile("cp.async.wait_group 0;\n" ::: "memory");
        }
        __syncthreads();                 // buf p visible

        const uint32_t* Ah = smG + p * GSTG;
        const uint32_t* Al = Ah + GMAT;
        const uint32_t* Bh = Ah + 2 * GMAT;
        const uint32_t* Bl = Ah + 3 * GMAT;

#pragma unroll
        for (int ks = 0; ks < 2; ks++) {
            const int kc = ks * 8 + c4;
            uint32_t ah[2][4], al[2][4];
#pragma unroll
            for (int i = 0; i < 2; i++) {
                const int r = wm + i * 16 + g;
                ah[i][0] = Ah[r * GSTR2 + kc];       ah[i][1] = Ah[(r + 8) * GSTR2 + kc];
                ah[i][2] = Ah[r * GSTR2 + kc + 4];   ah[i][3] = Ah[(r + 8) * GSTR2 + kc + 4];
                al[i][0] = Al[r * GSTR2 + kc];       al[i][1] = Al[(r + 8) * GSTR2 + kc];
                al[i][2] = Al[r * GSTR2 + kc + 4];   al[i][3] = Al[(r + 8) * GSTR2 + kc + 4];
            }
#pragma unroll
            for (int j = 0; j < 8; j++) {
                const int n = wn + j * 8 + g;
                uint32_t bh0 = Bh[n * GSTR2 + kc], bh1 = Bh[n * GSTR2 + kc + 4];
                uint32_t bl0 = Bl[n * GSTR2 + kc], bl1 = Bl[n * GSTR2 + kc + 4];
#pragma unroll
                for (int i = 0; i < 2; i++) {
                    mma_bf16(acc[i][j], ah[i][0], ah[i][1], ah[i][2], ah[i][3], bh0, bh1);
                    mma_bf16(acc[i][j], ah[i][0], ah[i][1], ah[i][2], ah[i][3], bl0, bl1);
                    mma_bf16(acc[i][j], al[i][0], al[i][1], al[i][2], al[i][3], bh0, bh1);
                }
            }
        }
    }

#pragma unroll
    for (int i = 0; i < 2; i++) {
        const int r0 = bm + wm + i * 16 + g;
#pragma unroll
        for (int j = 0; j < 8; j++) {
            const int cc = bn + wn + j * 8 + c4 * 2;
            *(float2*)(C + (size_t)r0 * ldc + cc)       = make_float2(acc[i][j][0], acc[i][j][1]);
            *(float2*)(C + (size_t)(r0 + 8) * ldc + cc) = make_float2(acc[i][j][2], acc[i][j][3]);
        }
    }
}

// ---------------------------------------------------------------------------
// RoPE (proven).
// ---------------------------------------------------------------------------
__global__ void rope_kernel(float* __restrict__ qkv, const int* __restrict__ pos_ids)
{
    const int s = blockIdx.x;
    const int d = threadIdx.x;
    const double invf = exp(-(double)d * (9.210340371976184 / 128.0));
    const double ang  = (double)pos_ids[s] * invf;
    const float c  = (float)cos(ang);
    const float si = (float)sin(ang);

    float* row = qkv + (size_t)s * QKVN;
#pragma unroll
    for (int head = 0; head < 12; head++) {
        const int base = head * 256;
        const float x0 = row[base + d];
        const float x1 = row[base + d + 128];
        row[base + d]       = x0 * c - x1 * si;
        row[base + d + 128] = x1 * c + x0 * si;
    }
}

// ---------------------------------------------------------------------------
// prep_split (proven): one-time K/V hi/lo split, V transposed.
// ---------------------------------------------------------------------------
__global__ void __launch_bounds__(256) prep_split(const float* __restrict__ qkv)
{
    __shared__ unsigned short sVh[32][260], sVl[32][260];

    const int kvh = blockIdx.y;
    const int kt  = blockIdx.x * 32;
    const int tid = threadIdx.x;
    const int r   = tid >> 3;
    const int cb  = (tid & 7) * 32;

    const float* krow = qkv + (size_t)(kt + r) * QKVN + NH * HD + kvh * HD + cb;
    const float* vrow = krow + NKV * HD;
    uint32_t* khp = gKh + ((size_t)kvh * S_LEN + kt + r) * 128 + cb / 2;
    uint32_t* klp = gKl + ((size_t)kvh * S_LEN + kt + r) * 128 + cb / 2;

#pragma unroll
    for (int i = 0; i < 8; i++) {
        float4 kv = *(const float4*)(krow + i * 4);
        uint32_t h0, l0, h1, l1;
        split2(kv.x, kv.y, h0, l0);
        split2(kv.z, kv.w, h1, l1);
        khp[i * 2] = h0; khp[i * 2 + 1] = h1;
        klp[i * 2] = l0; klp[i * 2 + 1] = l1;

        float4 vv = *(const float4*)(vrow + i * 4);
        uint32_t vh0, vl0, vh1, vl1;
        split2(vv.x, vv.y, vh0, vl0);
        split2(vv.z, vv.w, vh1, vl1);
        *(uint32_t*)&sVh[r][cb + i * 4]     = vh0;
        *(uint32_t*)&sVh[r][cb + i * 4 + 2] = vh1;
        *(uint32_t*)&sVl[r][cb + i * 4]     = vl0;
        *(uint32_t*)&sVl[r][cb + i * 4 + 2] = vl1;
    }
    __syncthreads();

    const int d = tid;
    uint32_t* vhp = gVh + ((size_t)kvh * HD + d) * (S_LEN / 2) + kt / 2;
    uint32_t* vlp = gVl + ((size_t)kvh * HD + d) * (S_LEN / 2) + kt / 2;
#pragma unroll
    for (int j = 0; j < 16; j++) {
        vhp[j] = (uint32_t)sVh[2 * j][d] | ((uint32_t)sVh[2 * j + 1][d] << 16);
        vlp[j] = (uint32_t)sVl[2 * j][d] | ((uint32_t)sVl[2 * j + 1][d] << 16);
    }
}

// ---------------------------------------------------------------------------
// Tensor-core attention (R15-proven, unchanged).
// ---------------------------------------------------------------------------
#define AQ_STR 132
#define AP_STR 20
#define QH_OFF 0
#define QL_OFF (64 * AQ_STR)
#define K_OFF  (2 * 64 * AQ_STR)
#define KBUF_STR (2 * 32 * AQ_STR)
#define V_OFF  (K_OFF + 2 * KBUF_STR)
#define VBUF_STR (2 * 256 * 16)
#define P_OFF  (V_OFF + 2 * VBUF_STR)
#define ATTN_SMEM_U32 (P_OFF + 2 * 64 * AP_STR)
#define ATTN_SMEM_BYTES (ATTN_SMEM_U32 * 4)

__device__ __forceinline__ float softcap_p(float s, int gq, int gk)
{
    float a = ex2_approx(s * 0.05770780163555852f);
    float p = ex2_approx(-144.26950408889634f * rcp_approx(a + 1.0f));
    bool ok = (gk <= gq) && ((gq - gk) < SWIN);
    return ok ? p : 0.f;
}

__global__ void __launch_bounds__(256) attn_mma7(
    const float* __restrict__ qkv, float* __restrict__ ao)
{
    extern __shared__ uint32_t smA[];
    uint32_t* Qh = smA + QH_OFF;
    uint32_t* Ql = smA + QL_OFF;
    uint32_t* Ph = smA + P_OFF;
    uint32_t* Pl = smA + P_OFF + 64 * AP_STR;
    __shared__ float LS[2][64];

    const uint32_t smem_u32 = (uint32_t)__cvta_generic_to_shared(smA);

    const int h   = blockIdx.y;
    const int q0  = ((int)gridDim.x - 1 - (int)blockIdx.x) * 64;
    const int kvh = h >> 1;
    const int tid = threadIdx.x;
    const int warp = tid >> 5, lane = tid & 31;
    const int g = lane >> 2, c4 = lane & 3;
    const int wm  = (warp >> 1) * 16;
    const int wh  = warp & 1;
    const int pair_bar = 1 + (warp >> 1);

    const int lr = lane & 7;
    const int lm = lane >> 3;

    const int kr  = tid >> 3;
    const int kc  = (tid & 7) * 4;
    const int vdg = tid >> 2;
    const int vgp = tid & 3;
    const uint32_t* skh_b = gKh + ((size_t)kvh * S_LEN + kr) * 128 + kc;
    const uint32_t* skl_b = gKl + ((size_t)kvh * S_LEN + kr) * 128 + kc;
    const uint32_t* svh_b = gVh + ((size_t)kvh * HD) * (S_LEN / 2) + vgp * 4;
    const uint32_t* svl_b = gVl + ((size_t)kvh * HD) * (S_LEN / 2) + vgp * 4;

    {
        const int row = tid >> 2;
        const int cb  = (tid & 3) * 64;
        const float* qrow = qkv + (size_t)(q0 + row) * QKVN + h * HD + cb;
        uint32_t* qhp = Qh + row * AQ_STR + cb / 2;
        uint32_t* qlp = Ql + row * AQ_STR + cb / 2;
#pragma unroll
        for (int i = 0; i < 16; i++) {
            float4 v = *(const float4*)(qrow + i * 4);
            v.x *= SCALE_F; v.y *= SCALE_F; v.z *= SCALE_F; v.w *= SCALE_F;
            uint32_t h0, l0, h1, l1;
            split2(v.x, v.y, h0, l0);
            split2(v.z, v.w, h1, l1);
            qhp[i * 2] = h0; qhp[i * 2 + 1] = h1;
            qlp[i * 2] = l0; qlp[i * 2 + 1] = l1;
        }
    }

    const uint32_t qh_lb = smem_u32 + (QH_OFF + (wm + lr + (lm & 1) * 8) * AQ_STR + (lm >> 1) * 4) * 4;
    const uint32_t ql_lb = smem_u32 + (QL_OFF + (wm + lr + (lm & 1) * 8) * AQ_STR + (lm >> 1) * 4) * 4;
    const uint32_t ph_lb = smem_u32 + (P_OFF + (wm + lr + (lm & 1) * 8) * AP_STR + (lm >> 1) * 4) * 4;
    const uint32_t pl_lb = ph_lb + (64 * AP_STR) * 4;
    const uint32_t k_lrow = (wh * 16 + (lm >> 1) * 8 + lr) * AQ_STR + (lm & 1) * 4;

    float oacc[16][4];
#pragma unroll
    for (int nf = 0; nf < 16; nf++)
#pragma unroll
        for (int t = 0; t < 4; t++) oacc[nf][t] = 0.f;
    float lsum0 = 0.f, lsum1 = 0.f;

    int klo = q0 - (SWIN - 1);
    if (klo < 0) klo = 0;
    klo &= ~31;
    const int khi = q0 + 63;

    auto stage = [&](int kt_, int b) {
        const uint32_t kh_d = smem_u32 + (K_OFF + b * KBUF_STR + kr * AQ_STR + kc) * 4;
        const uint32_t kl_d = kh_d + (32 * AQ_STR) * 4;
        const uint32_t* skh = skh_b + (size_t)kt_ * 128;
        const uint32_t* skl = skl_b + (size_t)kt_ * 128;
#pragma unroll
        for (int i = 0; i < 4; i++) {
            cpa16(kh_d + i * 128, skh + i * 32);
            cpa16(kl_d + i * 128, skl + i * 32);
        }
        const uint32_t* svh = svh_b + (kt_ >> 1);
        const uint32_t* svl = svl_b + (kt_ >> 1);
#pragma unroll
        for (int pass = 0; pass < 4; pass++) {
            const int d = pass * 64 + vdg;
            const int idx = d * 16 + 4 * (vgp ^ ((d >> 1) & 3));
            const uint32_t vh_d = smem_u32 + (V_OFF + b * VBUF_STR + idx) * 4;
            const uint32_t vl_d = vh_d + (256 * 16) * 4;
            cpa16(vh_d, svh + (size_t)d * (S_LEN / 2));
            cpa16(vl_d, svl + (size_t)d * (S_LEN / 2));
        }
        asm volatile("cp.async.commit_group;\n" ::: "memory");
    };

    stage(klo, 0);

    int ti = 0;
    for (int kt = klo; kt <= khi; kt += 32, ti++) {
        __syncthreads();
        const bool more = (kt + 32 <= khi);
        if (more) {
            stage(kt + 32, (ti + 1) & 1);
            asm volatile("cp.async.wait_group 1;\n" ::: "memory");
        } else {
            asm volatile("cp.async.wait_group 0;\n" ::: "memory");
        }
        __syncthreads();

        const uint32_t kh_lb = smem_u32 + (K_OFF + (ti & 1) * KBUF_STR + k_lrow) * 4;
        const uint32_t kl_lb = kh_lb + (32 * AQ_STR) * 4;
        const uint32_t vh_bb = smem_u32 + (V_OFF + (ti & 1) * VBUF_STR) * 4;
        const uint32_t vl_bb = vh_bb + (256 * 16) * 4;

        float sacc[2][2][4];
#pragma unroll
        for (int e = 0; e < 2; e++)
#pragma unroll
            for (int f = 0; f < 2; f++)
#pragma unroll
                for (int t = 0; t < 4; t++) sacc[e][f][t] = 0.f;

#pragma unroll 4
        for (int ks = 0; ks < 16; ks++) {
            const uint32_t koff = (uint32_t)(ks * 8 * 4);
            uint32_t ah0, ah1, ah2, ah3, al0, al1, al2, al3;
            ldsm4(ah0, ah1, ah2, ah3, qh_lb + koff);
            ldsm4(al0, al1, al2, al3, ql_lb + koff);
            uint32_t bh00, bh10, bh01, bh11, bl00, bl10, bl01, bl11;
            ldsm4(bh00, bh10, bh01, bh11, kh_lb + koff);
            ldsm4(bl00, bl10, bl01, bl11, kl_lb + koff);
            float* s0 = sacc[ks & 1][0];
            float* s1 = sacc[ks & 1][1];
            mma_bf16(s0, ah0, ah1, ah2, ah3, bh00, bh10);
            mma_bf16(s1, ah0, ah1, ah2, ah3, bh01, bh11);
            mma_bf16(s0, ah0, ah1, ah2, ah3, bl00, bl10);
            mma_bf16(s1, ah0, ah1, ah2, ah3, bl01, bl11);
            mma_bf16(s0, al0, al1, al2, al3, bh00, bh10);
            mma_bf16(s1, al0, al1, al2, al3, bh01, bh11);
        }
#pragma unroll
        for (int f = 0; f < 2; f++)
#pragma unroll
            for (int t = 0; t < 4; t++) sacc[0][f][t] += sacc[1][f][t];

        {
            const int r0 = q0 + wm + g;
            const int kb0 = kt + wh * 16 + 2 * c4;
#pragma unroll
            for (int f = 0; f < 2; f++) {
                const int kk = kb0 + f * 8;
                float p00 = softcap_p(sacc[0][f][0], r0, kk);
                float p01 = softcap_p(sacc[0][f][1], r0, kk + 1);
                float p10 = softcap_p(sacc[0][f][2], r0 + 8, kk);
                float p11 = softcap_p(sacc[0][f][3], r0 + 8, kk + 1);
                lsum0 += p00 + p01;
                lsum1 += p10 + p11;
                uint32_t hi, lo;
                split2(p00, p01, hi, lo);
                Ph[(wm + g) * AP_STR + wh * 8 + f * 4 + c4] = hi;
                Pl[(wm + g) * AP_STR + wh * 8 + f * 4 + c4] = lo;
                split2(p10, p11, hi, lo);
                Ph[(wm + g + 8) * AP_STR + wh * 8 + f * 4 + c4] = hi;
                Pl[(wm + g + 8) * AP_STR + wh * 8 + f * 4 + c4] = lo;
            }
        }
        asm volatile("bar.sync %0, 64;" :: "r"(pair_bar) : "memory");

#pragma unroll
        for (int ks2 = 0; ks2 < 2; ks2++) {
            uint32_t pah0, pah1, pah2, pah3, pal0, pal1, pal2, pal3;
            ldsm4(pah0, pah1, pah2, pah3, ph_lb + (uint32_t)(ks2 * 8 * 4));
            ldsm4(pal0, pal1, pal2, pal3, pl_lb + (uint32_t)(ks2 * 8 * 4));
#pragma unroll
            for (int nfp = 0; nfp < 8; nfp++) {
                const int dn  = wh * 128 + (2 * nfp + (lm >> 1)) * 8 + lr;
                const int swl = (dn >> 1) & 3;
                const uint32_t voff =
                    (uint32_t)((dn * 16 + 4 * ((2 * ks2 + (lm & 1)) ^ swl)) * 4);
                uint32_t va0, va1, vb0, vb1, wa0, wa1, wb0, wb1;
                ldsm4(va0, va1, vb0, vb1, vh_bb + voff);
                ldsm4(wa0, wa1, wb0, wb1, vl_bb + voff);
                float* o0 = oacc[2 * nfp];
                float* o1 = oacc[2 * nfp + 1];
                mma_bf16(o0, pah0, pah1, pah2, pah3, va0, va1);
                mma_bf16(o1, pah0, pah1, pah2, pah3, vb0, vb1);
                mma_bf16(o0, pah0, pah1, pah2, pah3, wa0, wa1);
                mma_bf16(o1, pah0, pah1, pah2, pah3, wb0, wb1);
                mma_bf16(o0, pal0, pal1, pal2, pal3, va0, va1);
                mma_bf16(o1, pal0, pal1, pal2, pal3, vb0, vb1);
            }
        }
    }

    lsum0 += __shfl_xor_sync(0xffffffffu, lsum0, 1);
    lsum0 += __shfl_xor_sync(0xffffffffu, lsum0, 2);
    lsum1 += __shfl_xor_sync(0xffffffffu, lsum1, 1);
    lsum1 += __shfl_xor_sync(0xffffffffu, lsum1, 2);
    if (c4 == 0) {
        LS[wh][wm + g]     = lsum0;
        LS[wh][wm + g + 8] = lsum1;
    }
    __syncthreads();
    const float inv0 = 1.0f / (LS[0][wm + g] + LS[1][wm + g]);
    const float inv1 = 1.0f / (LS[0][wm + g + 8] + LS[1][wm + g + 8]);

    {
        float* r0p = ao + (size_t)(q0 + wm + g) * (NH * HD) + h * HD + wh * 128;
        float* r1p = ao + (size_t)(q0 + wm + g + 8) * (NH * HD) + h * HD + wh * 128;
#pragma unroll
        for (int nf = 0; nf < 16; nf++) {
            const int dc = nf * 8 + 2 * c4;
            *(float2*)(r0p + dc) = make_float2(oacc[nf][0] * inv0, oacc[nf][1] * inv0);
            *(float2*)(r1p + dc) = make_float2(oacc[nf][2] * inv1, oacc[nf][3] * inv1);
        }
    }
}

// ---------------------------------------------------------------------------
// Inputs: hidden f32 [1,4096,2304], mask (ignored — analytic), Wq [2048,2304],
// Wk [1024,2304], Wv [1024,2304], Wo [2304,2048], position_ids i32 [1,4096].
// ---------------------------------------------------------------------------
extern "C" void kernel_launch(void* const* d_in, const int* in_sizes, int n_in,
                              void* d_out, int out_size)
{
    const float* hidden = (const float*)d_in[0];
    const float* Wq     = (const float*)d_in[2];
    const float* Wk     = (const float*)d_in[3];
    const float* Wv     = (const float*)d_in[4];
    const float* Wo     = (const float*)d_in[5];
    const int*   pos    = (const int*)d_in[6];
    float*       out    = (float*)d_out;

    float *qkv, *ao;
    uint32_t *xh, *xl, *wh, *wl, *oh, *ol, *woh, *wol;
    cudaGetSymbolAddress((void**)&qkv, g_qkv);
    cudaGetSymbolAddress((void**)&ao,  g_ao);
    cudaGetSymbolAddress((void**)&xh,  gXh);  cudaGetSymbolAddress((void**)&xl,  gXl);
    cudaGetSymbolAddress((void**)&wh,  gWh);  cudaGetSymbolAddress((void**)&wl,  gWl);
    cudaGetSymbolAddress((void**)&oh,  gOh);  cudaGetSymbolAddress((void**)&ol,  gOl);
    cudaGetSymbolAddress((void**)&woh, gWoh); cudaGetSymbolAddress((void**)&wol, gWol);

    cudaFuncSetAttribute(gemm_bf16p, cudaFuncAttributeMaxDynamicSharedMemorySize, GEMM_SMEM_BYTES);
    cudaFuncSetAttribute(attn_mma7, cudaFuncAttributeMaxDynamicSharedMemorySize, ATTN_SMEM_BYTES);

    // Pre-split GEMM operands to bf16 hi/lo (once; amortized across CTAs)
    split_mat<<<4096, 256>>>(hidden, xh, xl, KU_A);
    split_mat<<<2048, 256>>>(Wq, wh, wl, KU_A);
    split_mat<<<1024, 256>>>(Wk, wh + (size_t)2048 * KU_A, wl + (size_t)2048 * KU_A, KU_A);
    split_mat<<<1024, 256>>>(Wv, wh + (size_t)3072 * KU_A, wl + (size_t)3072 * KU_A, KU_A);
    split_mat<<<2304, 256>>>(Wo, woh, wol, KU_O);

    // QKV projection: ONE fused cp.async-pipelined launch (N=4096 columns)
    gemm_bf16p<<<dim3(32, 32), 256, GEMM_SMEM_BYTES>>>(xh, xl, wh, wl, qkv, HIDDEN, KU_A, QKVN);

    // RoPE + attention pre-split (proven)
    rope_kernel<<<S_LEN, 128>>>(qkv, pos);
    prep_split<<<dim3(S_LEN / 32, NKV), 256>>>(qkv);

    // Attention (R15-proven)
    attn_mma7<<<dim3(S_LEN / 64, NH), 256, ATTN_SMEM_BYTES>>>(qkv, ao);

    // Output projection: pre-split + pipelined GEMM
    split_mat<<<4096, 256>>>(ao, oh, ol, KU_O);
    gemm_bf16p<<<dim3(18, 32), 256, GEMM_SMEM_BYTES>>>(oh, ol, woh, wol, out, NH * HD, KU_O, HIDDEN);
}